// round 6
// baseline (speedup 1.0000x reference)
#include <cuda_runtime.h>
#include <math.h>
#include <cstdint>

#define BATCH 4
#define CIN   64
#define HH    160
#define WW    160
#define GRP   8
#define KK9   9
#define CG    8
#define HW    (HH*WW)

// scratch: dy, dx, mask each [B][G*9][H][W]
#define SCR_N (BATCH*GRP*KK9*HH*WW)   // 7,372,800
__device__ float g_scr[3*SCR_N];

// pre-packed tf32 B fragments: [t(72)][ntp(28)][lane(32)] float2 (tile 27 = zero pad)
#define NTP 28
#define NBT_VALID (72*27*32)
__device__ float2 g_bfrag[72*NTP*32];

__device__ __forceinline__ uint32_t f2tf32(float v) {
    uint32_t r;
    asm("cvt.rna.tf32.f32 %0, %1;" : "=r"(r) : "f"(v));
    return r;
}

#define MMA_TF32(d, a, b0, b1) \
    asm volatile("mma.sync.aligned.m16n8k8.row.col.f32.tf32.tf32.f32 " \
        "{%0,%1,%2,%3}, {%4,%5,%6,%7}, {%8,%9}, {%0,%1,%2,%3};" \
        : "+f"((d)[0]), "+f"((d)[1]), "+f"((d)[2]), "+f"((d)[3]) \
        : "r"((a)[0]), "r"((a)[1]), "r"((a)[2]), "r"((a)[3]), \
          "r"(b0), "r"(b1))

// ---------------------------------------------------------------------------
// Pack w_off [216][64*9] into tf32 fragment order, K permuted kk-major:
// kd = kk*64 + ci  (A side uses the same permutation)
// ---------------------------------------------------------------------------
__global__ __launch_bounds__(256)
void pack_w_kernel(const float* __restrict__ w_off)
{
    int e = blockIdx.x * 256 + threadIdx.x;
    if (e >= NBT_VALID) return;
    int lane = e & 31;
    int r = e >> 5;
    int nt = r % 27;
    int t  = r / 27;                 // global ktile 0..71
    int n  = nt * 8 + (lane >> 2);
    int kd0 = t * 8 + (lane & 3);
    int kd1 = kd0 + 4;
    int ci0 = kd0 & 63, kk0 = kd0 >> 6;
    int ci1 = kd1 & 63, kk1 = kd1 >> 6;
    float2 v;
    v.x = __uint_as_float(f2tf32(w_off[(size_t)n * 576 + ci0 * 9 + kk0]));
    v.y = __uint_as_float(f2tf32(w_off[(size_t)n * 576 + ci1 * 9 + kk1]));
    g_bfrag[((size_t)t * NTP + nt) * 32 + lane] = v;
}

// ---------------------------------------------------------------------------
// Kernel A: implicit-GEMM 3x3 conv via mma.sync tf32
// 512 thr / 16 warps: warp pair shares m16 pixel rows, splits N=216 (14|13 nt)
// ---------------------------------------------------------------------------
__device__ __forceinline__ void emit_off(int co, float v, int b, int p,
                                         const float* __restrict__ b_off) {
    v += __ldg(b_off + co);
    if (co < 144) {
        int g = co / 18, r = co % 18, k = r >> 1;
        float* dst = (r & 1) ? (g_scr + SCR_N) : g_scr;   // dx : dy
        dst[(b * GRP * KK9 + g * KK9 + k) * HW + p] = v;
    } else {
        int cm = co - 144, g = cm / 9, k = cm % 9;
        g_scr[2 * SCR_N + (b * GRP * KK9 + g * KK9 + k) * HW + p] =
            1.f / (1.f + expf(-v));
    }
}

__global__ __launch_bounds__(512, 1)
void offset_conv_mma(const float* __restrict__ feat,
                     const float* __restrict__ b_off)
{
    const int tid  = threadIdx.x;
    const int warp = tid >> 5, lane = tid & 31;
    const int mtile = warp >> 1;        // 0..7
    const int half  = warp & 1;         // n-split
    const int b  = blockIdx.y;
    const int p0 = blockIdx.x * 128;

    const int m0 = mtile * 16 + (lane >> 2);
    const int pA = p0 + m0, pB = pA + 8;
    const int yA = pA / WW, xA = pA % WW;
    const int yB = pB / WW, xB = pB % WW;
    const float* fb = feat + (size_t)b * CIN * HW;

    float acc[14][4];
#pragma unroll
    for (int i = 0; i < 14; i++)
#pragma unroll
        for (int j = 0; j < 4; j++) acc[i][j] = 0.f;

    const int c = lane & 3;

    // sample pair for kd (kk-major: kd = kk*64 + ci): rows pA, pB
    auto samp2 = [&](int kd, float& vA, float& vB) {
        int kk = kd >> 6, ci = kd & 63;
        int dy = (kk > 5) ? 2 : ((kk > 2) ? 1 : 0);
        int dx = kk - dy * 3;
        int base = ci * HW;
        int gyA = yA + dy - 1, gxA = xA + dx - 1;
        int gyB = yB + dy - 1, gxB = xB + dx - 1;
        vA = ((unsigned)gyA < HH && (unsigned)gxA < WW)
               ? __ldg(fb + base + gyA * WW + gxA) : 0.f;
        vB = ((unsigned)gyB < HH && (unsigned)gxB < WW)
               ? __ldg(fb + base + gyB * WW + gxB) : 0.f;
    };

    uint32_t a[4];
    {
        float v0, v1, v2, v3;
        samp2(c, v0, v1);
        samp2(c + 4, v2, v3);
        a[0] = f2tf32(v0); a[1] = f2tf32(v1);
        a[2] = f2tf32(v2); a[3] = f2tf32(v3);
    }

    const float2* bp = g_bfrag + lane + (size_t)half * 14 * 32;

#pragma unroll 1
    for (int t = 0; t < 72; t++) {
        // prefetch next ktile's A fragment
        uint32_t an[4] = {0u, 0u, 0u, 0u};
        if (t < 71) {
            float v0, v1, v2, v3;
            samp2((t + 1) * 8 + c, v0, v1);
            samp2((t + 1) * 8 + c + 4, v2, v3);
            an[0] = f2tf32(v0); an[1] = f2tf32(v1);
            an[2] = f2tf32(v2); an[3] = f2tf32(v3);
        }

        const float2* bt = bp + (size_t)t * NTP * 32;
#pragma unroll
        for (int i = 0; i < 14; i++) {
            float2 bb = __ldg(bt + i * 32);
            MMA_TF32(acc[i], a, __float_as_uint(bb.x), __float_as_uint(bb.y));
        }

        a[0] = an[0]; a[1] = an[1]; a[2] = an[2]; a[3] = an[3];
    }

    // epilogue
#pragma unroll
    for (int i = 0; i < 14; i++) {
        int nt = half * 14 + i;
#pragma unroll
        for (int e = 0; e < 4; e++) {
            int co = nt * 8 + c * 2 + (e & 1);
            if (co < 216)
                emit_off(co, acc[i][e], b, (e >= 2) ? pB : pA, b_off);
        }
    }
}

// ---------------------------------------------------------------------------
// Kernel B: modulated deformable conv (unchanged, known-good)
// ---------------------------------------------------------------------------
__global__ __launch_bounds__(128)
void dcn_kernel(const float* __restrict__ xin,
                const float* __restrict__ w_dcn,
                const float* __restrict__ b_dcn,
                float* __restrict__ out)
{
    __shared__ float swt[CG*9*64];

    const int tx = threadIdx.x & 31;
    const int ty = threadIdx.x >> 5;
    const int x = blockIdx.x * 32 + tx;
    const int y = blockIdx.y * 4 + ty;
    const int b = blockIdx.z;

    float acc[64];
#pragma unroll
    for (int o = 0; o < 64; o++) acc[o] = 0.f;

    const float* dyp = g_scr;
    const float* dxp = g_scr + SCR_N;
    const float* mp  = g_scr + 2*SCR_N;

    for (int g = 0; g < GRP; g++) {
        __syncthreads();
        for (int idx = threadIdx.x; idx < CG*9*64; idx += 128) {
            int o = idx & 63;
            int r = idx >> 6;
            int c = r / 9, k = r % 9;
            swt[idx] = w_dcn[((size_t)o*CIN + (g*CG + c))*9 + k];
        }
        __syncthreads();

        const float* xg = xin + ((size_t)b*CIN + g*CG) * HW;

#pragma unroll 1
        for (int k = 0; k < 9; k++) {
            int oidx = ((b*GRP*KK9 + g*KK9 + k)*HH + y)*WW + x;
            float dy = dyp[oidx], dx = dxp[oidx], mv = mp[oidx];
            float py = (float)y + (float)(k/3 - 1) + dy;
            float px = (float)x + (float)(k%3 - 1) + dx;
            float fy = floorf(py), fx = floorf(px);
            int y0 = (int)fy, x0 = (int)fx;
            float ly = py - fy, lx = px - fx;

            bool vy0 = (y0   >= 0 && y0   < HH);
            bool vy1 = (y0+1 >= 0 && y0+1 < HH);
            bool vx0 = (x0   >= 0 && x0   < WW);
            bool vx1 = (x0+1 >= 0 && x0+1 < WW);
            int y0c = min(max(y0,   0), HH-1);
            int y1c = min(max(y0+1, 0), HH-1);
            int x0c = min(max(x0,   0), WW-1);
            int x1c = min(max(x0+1, 0), WW-1);

            float w00 = (1.f-ly)*(1.f-lx)*mv * ((vy0 && vx0) ? 1.f : 0.f);
            float w01 = (1.f-ly)*lx      *mv * ((vy0 && vx1) ? 1.f : 0.f);
            float w10 = ly      *(1.f-lx)*mv * ((vy1 && vx0) ? 1.f : 0.f);
            float w11 = ly      *lx      *mv * ((vy1 && vx1) ? 1.f : 0.f);

            int i00 = y0c*WW + x0c, i01 = y0c*WW + x1c;
            int i10 = y1c*WW + x0c, i11 = y1c*WW + x1c;

            float vv[CG];
#pragma unroll
            for (int c = 0; c < CG; c++) {
                const float* xc = xg + c*HW;
                vv[c] = w00*xc[i00] + w01*xc[i01] + w10*xc[i10] + w11*xc[i11];
            }
#pragma unroll
            for (int c = 0; c < CG; c++) {
                const float4* w4 = (const float4*)&swt[(c*9+k)*64];
                float v = vv[c];
#pragma unroll
                for (int q = 0; q < 16; q++) {
                    float4 w = w4[q];
                    acc[4*q+0] += w.x * v;
                    acc[4*q+1] += w.y * v;
                    acc[4*q+2] += w.z * v;
                    acc[4*q+3] += w.w * v;
                }
            }
        }
    }

#pragma unroll
    for (int o = 0; o < 64; o++)
        out[((b*64 + o)*HH + y)*WW + x] = acc[o] + b_dcn[o];
}

// ---------------------------------------------------------------------------
extern "C" void kernel_launch(void* const* d_in, const int* in_sizes, int n_in,
                              void* d_out, int out_size)
{
    const float* x     = (const float*)d_in[0];
    const float* feat  = (const float*)d_in[1];
    const float* w_off = (const float*)d_in[2];
    const float* b_off = (const float*)d_in[3];
    const float* w_dcn = (const float*)d_in[4];
    const float* b_dcn = (const float*)d_in[5];
    float* out = (float*)d_out;

    pack_w_kernel<<<(NBT_VALID + 255) / 256, 256>>>(w_off);

    dim3 gA(HW / 128, BATCH);           // 200 x 4
    offset_conv_mma<<<gA, 512>>>(feat, b_off);

    dim3 gB(WW/32, HH/4, BATCH);        // 5 x 40 x 4
    dcn_kernel<<<gB, 128>>>(x, w_dcn, b_dcn, out);
}

// round 7
// speedup vs baseline: 1.2245x; 1.2245x over previous
#include <cuda_runtime.h>
#include <math.h>
#include <cstdint>

#define BATCH 4
#define CIN   64
#define HH    160
#define WW    160
#define GRP   8
#define KK9   9
#define CG    8
#define HW    (HH*WW)

// scratch: dy, dx, mask each [B][G*9][H][W]
#define SCR_N (BATCH*GRP*KK9*HH*WW)   // 7,372,800
__device__ float g_scr[3*SCR_N];

// pre-packed tf32 B fragments for offset conv: [t(72)][nt(27)][lane(32)] float2
#define NBT (72*27*32)
__device__ float2 g_bfrag[NBT];

// pre-packed tf32 B fragments for dcn: [t(72)][nt(8)][lane(32)] float2
#define NBT2 (72*8*32)
__device__ float2 g_bfrag2[NBT2];

__device__ __forceinline__ uint32_t f2tf32(float v) {
    uint32_t r;
    asm("cvt.rna.tf32.f32 %0, %1;" : "=r"(r) : "f"(v));
    return r;
}

#define MMA_TF32(d, a, b0, b1) \
    asm volatile("mma.sync.aligned.m16n8k8.row.col.f32.tf32.tf32.f32 " \
        "{%0,%1,%2,%3}, {%4,%5,%6,%7}, {%8,%9}, {%0,%1,%2,%3};" \
        : "+f"((d)[0]), "+f"((d)[1]), "+f"((d)[2]), "+f"((d)[3]) \
        : "r"((a)[0]), "r"((a)[1]), "r"((a)[2]), "r"((a)[3]), \
          "r"(b0), "r"(b1))

// ---------------------------------------------------------------------------
// Pack w_off [216][64*9] into tf32 fragment order (kd = ci*9 + kk, natural)
// ---------------------------------------------------------------------------
__global__ __launch_bounds__(256)
void pack_w_kernel(const float* __restrict__ w_off)
{
    int e = blockIdx.x * 256 + threadIdx.x;
    if (e >= NBT) return;
    int lane = e & 31;
    int r = e >> 5;
    int nt = r % 27;
    int t  = r / 27;                 // global ktile 0..71
    int n = nt * 8 + (lane >> 2);
    int k = t * 8 + (lane & 3);
    float2 v;
    v.x = __uint_as_float(f2tf32(w_off[(size_t)n * 576 + k]));
    v.y = __uint_as_float(f2tf32(w_off[(size_t)n * 576 + k + 4]));
    g_bfrag[e] = v;
}

// ---------------------------------------------------------------------------
// Pack w_dcn [64][64][3][3] into tf32 fragments, kd = (g*9+k)*8 + c
// ---------------------------------------------------------------------------
__global__ __launch_bounds__(256)
void pack_wd_kernel(const float* __restrict__ w_dcn)
{
    int e = blockIdx.x * 256 + threadIdx.x;
    if (e >= NBT2) return;
    int lane = e & 31;
    int r = e >> 5;
    int nt = r & 7;
    int t  = r >> 3;                 // ktile 0..71 = g*9+k
    int g = t / 9, k = t % 9;
    int n = nt * 8 + (lane >> 2);
    int c = lane & 3;
    float2 v;
    v.x = __uint_as_float(f2tf32(w_dcn[((size_t)n * CIN + g * 8 + c) * 9 + k]));
    v.y = __uint_as_float(f2tf32(w_dcn[((size_t)n * CIN + g * 8 + c + 4) * 9 + k]));
    g_bfrag2[e] = v;
}

// ---------------------------------------------------------------------------
// Kernel A: implicit-GEMM 3x3 conv via mma.sync tf32 (R3 verbatim, 440us)
// M=128 pixels/block (8 warps x m16), N=216 (27 n-tiles), K=576 (72 ktiles)
// ---------------------------------------------------------------------------
__device__ __forceinline__ void emit_off(int co, float v, int b, int p,
                                         const float* __restrict__ b_off) {
    v += __ldg(b_off + co);
    if (co < 144) {
        int g = co / 18, r = co % 18, k = r >> 1;
        float* dst = (r & 1) ? (g_scr + SCR_N) : g_scr;   // dx : dy
        dst[(b * GRP * KK9 + g * KK9 + k) * HW + p] = v;
    } else {
        int cm = co - 144, g = cm / 9, k = cm % 9;
        g_scr[2 * SCR_N + (b * GRP * KK9 + g * KK9 + k) * HW + p] =
            1.f / (1.f + expf(-v));
    }
}

__global__ __launch_bounds__(256)
void offset_conv_mma(const float* __restrict__ feat,
                     const float* __restrict__ b_off)
{
    const int tid  = threadIdx.x;
    const int warp = tid >> 5, lane = tid & 31;
    const int b  = blockIdx.y;
    const int p0 = blockIdx.x * 128;

    const int m0 = warp * 16 + (lane >> 2);
    const int pA = p0 + m0, pB = pA + 8;
    const int yA = pA / WW, xA = pA % WW;
    const int yB = pB / WW, xB = pB % WW;
    const float* fb = feat + (size_t)b * CIN * HW;

    float acc[27][4];
#pragma unroll
    for (int i = 0; i < 27; i++)
#pragma unroll
        for (int j = 0; j < 4; j++) acc[i][j] = 0.f;

    const int c = lane & 3;
    int ci0 = 0, kk0 = c;        // k-sequence: c, c+8, c+16, ...
    int ci1 = 0, kk1 = c + 4;    // k-sequence: c+4, c+12, ...

    auto samp2 = [&](int ci, int kk, float& vA, float& vB) {
        int dy = (kk > 5) ? 2 : ((kk > 2) ? 1 : 0);
        int dx = kk - dy * 3;
        int base = ci * HW;
        int gyA = yA + dy - 1, gxA = xA + dx - 1;
        int gyB = yB + dy - 1, gxB = xB + dx - 1;
        vA = ((unsigned)gyA < HH && (unsigned)gxA < WW)
               ? __ldg(fb + base + gyA * WW + gxA) : 0.f;
        vB = ((unsigned)gyB < HH && (unsigned)gxB < WW)
               ? __ldg(fb + base + gyB * WW + gxB) : 0.f;
    };

    uint32_t a[4];
    {
        float v0, v1, v2, v3;
        samp2(ci0, kk0, v0, v1);
        samp2(ci1, kk1, v2, v3);
        a[0] = f2tf32(v0); a[1] = f2tf32(v1);
        a[2] = f2tf32(v2); a[3] = f2tf32(v3);
    }

    const float2* bp = g_bfrag + lane;

#pragma unroll 1
    for (int t = 0; t < 72; t++) {
        uint32_t an[4] = {0u, 0u, 0u, 0u};
        if (t < 71) {
            if (kk0 == 0) kk0 = 8; else { kk0--; ci0++; }
            if (kk1 == 0) kk1 = 8; else { kk1--; ci1++; }
            float v0, v1, v2, v3;
            samp2(ci0, kk0, v0, v1);
            samp2(ci1, kk1, v2, v3);
            an[0] = f2tf32(v0); an[1] = f2tf32(v1);
            an[2] = f2tf32(v2); an[3] = f2tf32(v3);
        }

        const float2* bt = bp + (size_t)t * 27 * 32;
#pragma unroll
        for (int nt = 0; nt < 27; nt++) {
            float2 bb = __ldg(bt + nt * 32);
            MMA_TF32(acc[nt], a, __float_as_uint(bb.x), __float_as_uint(bb.y));
        }

        a[0] = an[0]; a[1] = an[1]; a[2] = an[2]; a[3] = an[3];
    }

#pragma unroll
    for (int nt = 0; nt < 27; nt++) {
#pragma unroll
        for (int i = 0; i < 4; i++) {
            int p  = (i >= 2) ? pB : pA;
            int co = nt * 8 + (lane & 3) * 2 + (i & 1);
            emit_off(co, acc[nt][i], b, p, b_off);
        }
    }
}

// ---------------------------------------------------------------------------
// Kernel B: modulated deformable conv via mma.sync tf32
// M=128 pixels/block, N=64 (8 n-tiles), K=576; ktile t=(g,k), lanes cover 8 ch
// ---------------------------------------------------------------------------
__global__ __launch_bounds__(256)
void dcn_mma(const float* __restrict__ xin,
             const float* __restrict__ b_dcn,
             float* __restrict__ out)
{
    const int tid  = threadIdx.x;
    const int warp = tid >> 5, lane = tid & 31;
    const int b  = blockIdx.y;
    const int p0 = blockIdx.x * 128;

    const int m0 = warp * 16 + (lane >> 2);
    const int pA = p0 + m0, pB = pA + 8;
    const int yA = pA / WW, xA = pA % WW;
    const int yB = pB / WW, xB = pB % WW;

    const float* dyp = g_scr;
    const float* dxp = g_scr + SCR_N;
    const float* mp  = g_scr + 2*SCR_N;
    const float* xb  = xin + (size_t)b * CIN * HW;

    float acc[8][4];
#pragma unroll
    for (int i = 0; i < 8; i++)
#pragma unroll
        for (int j = 0; j < 4; j++) acc[i][j] = 0.f;

    const int c = lane & 3;

    // build A fragment for ktile t = g*9+k: sample channels c, c+4 at rows pA,pB
    auto build_a = [&](int t, uint32_t* a) {
        int g = t / 9, k = t - g * 9;
        int kdy = (k > 5) ? 2 : ((k > 2) ? 1 : 0);
        int kdx = k - kdy * 3;
        const int sb = (b * 72 + t) * HW;
        const float* xc0 = xb + ((size_t)(g * 8 + c)) * HW;
        const float* xc4 = xc0 + 4 * HW;

        float vA0, vA4, vB0, vB4;
        {   // row pA
            float dy = __ldg(dyp + sb + pA), dx = __ldg(dxp + sb + pA);
            float mv = __ldg(mp + sb + pA);
            float py = (float)(yA + kdy - 1) + dy;
            float px = (float)(xA + kdx - 1) + dx;
            float fy = floorf(py), fx = floorf(px);
            int y0 = (int)fy, x0 = (int)fx;
            float ly = py - fy, lx = px - fx;
            bool vy0 = ((unsigned)y0 < HH), vy1 = ((unsigned)(y0+1) < HH);
            bool vx0 = ((unsigned)x0 < WW), vx1 = ((unsigned)(x0+1) < WW);
            int y0c = min(max(y0,0),HH-1), y1c = min(max(y0+1,0),HH-1);
            int x0c = min(max(x0,0),WW-1), x1c = min(max(x0+1,0),WW-1);
            float w00 = (1.f-ly)*(1.f-lx)*mv*((vy0&&vx0)?1.f:0.f);
            float w01 = (1.f-ly)*lx      *mv*((vy0&&vx1)?1.f:0.f);
            float w10 = ly      *(1.f-lx)*mv*((vy1&&vx0)?1.f:0.f);
            float w11 = ly      *lx      *mv*((vy1&&vx1)?1.f:0.f);
            int i00 = y0c*WW+x0c, i01 = y0c*WW+x1c;
            int i10 = y1c*WW+x0c, i11 = y1c*WW+x1c;
            vA0 = w00*__ldg(xc0+i00)+w01*__ldg(xc0+i01)+w10*__ldg(xc0+i10)+w11*__ldg(xc0+i11);
            vA4 = w00*__ldg(xc4+i00)+w01*__ldg(xc4+i01)+w10*__ldg(xc4+i10)+w11*__ldg(xc4+i11);
        }
        {   // row pB
            float dy = __ldg(dyp + sb + pB), dx = __ldg(dxp + sb + pB);
            float mv = __ldg(mp + sb + pB);
            float py = (float)(yB + kdy - 1) + dy;
            float px = (float)(xB + kdx - 1) + dx;
            float fy = floorf(py), fx = floorf(px);
            int y0 = (int)fy, x0 = (int)fx;
            float ly = py - fy, lx = px - fx;
            bool vy0 = ((unsigned)y0 < HH), vy1 = ((unsigned)(y0+1) < HH);
            bool vx0 = ((unsigned)x0 < WW), vx1 = ((unsigned)(x0+1) < WW);
            int y0c = min(max(y0,0),HH-1), y1c = min(max(y0+1,0),HH-1);
            int x0c = min(max(x0,0),WW-1), x1c = min(max(x0+1,0),WW-1);
            float w00 = (1.f-ly)*(1.f-lx)*mv*((vy0&&vx0)?1.f:0.f);
            float w01 = (1.f-ly)*lx      *mv*((vy0&&vx1)?1.f:0.f);
            float w10 = ly      *(1.f-lx)*mv*((vy1&&vx0)?1.f:0.f);
            float w11 = ly      *lx      *mv*((vy1&&vx1)?1.f:0.f);
            int i00 = y0c*WW+x0c, i01 = y0c*WW+x1c;
            int i10 = y1c*WW+x0c, i11 = y1c*WW+x1c;
            vB0 = w00*__ldg(xc0+i00)+w01*__ldg(xc0+i01)+w10*__ldg(xc0+i10)+w11*__ldg(xc0+i11);
            vB4 = w00*__ldg(xc4+i00)+w01*__ldg(xc4+i01)+w10*__ldg(xc4+i10)+w11*__ldg(xc4+i11);
        }
        a[0] = f2tf32(vA0); a[1] = f2tf32(vB0);
        a[2] = f2tf32(vA4); a[3] = f2tf32(vB4);
    };

    uint32_t a[4];
    build_a(0, a);

    const float2* bp = g_bfrag2 + lane;

#pragma unroll 1
    for (int t = 0; t < 72; t++) {
        uint32_t an[4] = {0u, 0u, 0u, 0u};
        if (t < 71) build_a(t + 1, an);

        const float2* bt = bp + (size_t)t * 8 * 32;
#pragma unroll
        for (int nt = 0; nt < 8; nt++) {
            float2 bb = __ldg(bt + nt * 32);
            MMA_TF32(acc[nt], a, __float_as_uint(bb.x), __float_as_uint(bb.y));
        }

        a[0] = an[0]; a[1] = an[1]; a[2] = an[2]; a[3] = an[3];
    }

    // epilogue: out[b][o][p]
#pragma unroll
    for (int nt = 0; nt < 8; nt++) {
#pragma unroll
        for (int e = 0; e < 4; e++) {
            int o = nt * 8 + c * 2 + (e & 1);
            int p = (e >= 2) ? pB : pA;
            out[((size_t)b * 64 + o) * HW + p] = acc[nt][e] + __ldg(b_dcn + o);
        }
    }
}

// ---------------------------------------------------------------------------
extern "C" void kernel_launch(void* const* d_in, const int* in_sizes, int n_in,
                              void* d_out, int out_size)
{
    const float* x     = (const float*)d_in[0];
    const float* feat  = (const float*)d_in[1];
    const float* w_off = (const float*)d_in[2];
    const float* b_off = (const float*)d_in[3];
    const float* w_dcn = (const float*)d_in[4];
    const float* b_dcn = (const float*)d_in[5];
    float* out = (float*)d_out;

    pack_w_kernel<<<(NBT + 255) / 256, 256>>>(w_off);
    pack_wd_kernel<<<(NBT2 + 255) / 256, 256>>>(w_dcn);

    dim3 gA(HW / 128, BATCH);           // 200 x 4
    offset_conv_mma<<<gA, 256>>>(feat, b_off);

    dim3 gB(HW / 128, BATCH);           // 200 x 4
    dcn_mma<<<gB, 256>>>(x, b_dcn, out);
}

// round 8
// speedup vs baseline: 1.6995x; 1.3880x over previous
#include <cuda_runtime.h>
#include <math.h>
#include <cstdint>

#define BATCH 4
#define CIN   64
#define HH    160
#define WW    160
#define GRP   8
#define KK9   9
#define CG    8
#define HW    (HH*WW)

// scratch: dy, dx, mask each [B][G*9][H][W]
#define SCR_N (BATCH*GRP*KK9*HH*WW)   // 7,372,800
__device__ float g_scr[3*SCR_N];

// NHWC transpose of x: [B][HW][CIN]
__device__ float g_xt[(size_t)BATCH*HW*CIN];

// pre-packed tf32 B fragments for offset conv: [t(72)][nt(27)][lane(32)] float2
#define NBT (72*27*32)
__device__ float2 g_bfrag[NBT];

// pre-packed tf32 B fragments for dcn: [t(72)][nt(8)][lane(32)] float2
#define NBT2 (72*8*32)
__device__ float2 g_bfrag2[NBT2];

__device__ __forceinline__ uint32_t f2tf32(float v) {
    uint32_t r;
    asm("cvt.rna.tf32.f32 %0, %1;" : "=r"(r) : "f"(v));
    return r;
}

#define MMA_TF32(d, a, b0, b1) \
    asm volatile("mma.sync.aligned.m16n8k8.row.col.f32.tf32.tf32.f32 " \
        "{%0,%1,%2,%3}, {%4,%5,%6,%7}, {%8,%9}, {%0,%1,%2,%3};" \
        : "+f"((d)[0]), "+f"((d)[1]), "+f"((d)[2]), "+f"((d)[3]) \
        : "r"((a)[0]), "r"((a)[1]), "r"((a)[2]), "r"((a)[3]), \
          "r"(b0), "r"(b1))

// ---------------------------------------------------------------------------
// Transpose x NCHW -> NHWC (g_xt)
// ---------------------------------------------------------------------------
__global__ __launch_bounds__(256)
void transpose_x_kernel(const float* __restrict__ xin)
{
    __shared__ float tile[32][33];
    const int b  = blockIdx.z;
    const int c0 = blockIdx.y * 32;          // 2 c-tiles
    const int p0 = blockIdx.x * 32;          // 800 p-tiles
    const int tx = threadIdx.x & 31;
    const int ty = threadIdx.x >> 5;         // 0..7

    const float* xb = xin + (size_t)b * CIN * HW;
#pragma unroll
    for (int j = 0; j < 4; j++)
        tile[ty + 8*j][tx] = xb[(size_t)(c0 + ty + 8*j) * HW + p0 + tx];
    __syncthreads();
    float* xo = g_xt + (size_t)b * HW * CIN;
#pragma unroll
    for (int j = 0; j < 4; j++)
        xo[(size_t)(p0 + ty + 8*j) * CIN + c0 + tx] = tile[tx][ty + 8*j];
}

// ---------------------------------------------------------------------------
// Pack w_off [216][64*9] into tf32 fragment order (kd = ci*9 + kk, natural)
// ---------------------------------------------------------------------------
__global__ __launch_bounds__(256)
void pack_w_kernel(const float* __restrict__ w_off)
{
    int e = blockIdx.x * 256 + threadIdx.x;
    if (e >= NBT) return;
    int lane = e & 31;
    int r = e >> 5;
    int nt = r % 27;
    int t  = r / 27;                 // global ktile 0..71
    int n = nt * 8 + (lane >> 2);
    int k = t * 8 + (lane & 3);
    float2 v;
    v.x = __uint_as_float(f2tf32(w_off[(size_t)n * 576 + k]));
    v.y = __uint_as_float(f2tf32(w_off[(size_t)n * 576 + k + 4]));
    g_bfrag[e] = v;
}

// ---------------------------------------------------------------------------
// Pack w_dcn [64][64][3][3] into tf32 fragments, kd = (g*9+k)*8 + c
// ---------------------------------------------------------------------------
__global__ __launch_bounds__(256)
void pack_wd_kernel(const float* __restrict__ w_dcn)
{
    int e = blockIdx.x * 256 + threadIdx.x;
    if (e >= NBT2) return;
    int lane = e & 31;
    int r = e >> 5;
    int nt = r & 7;
    int t  = r >> 3;                 // ktile 0..71 = g*9+k
    int g = t / 9, k = t % 9;
    int n = nt * 8 + (lane >> 2);
    int c = lane & 3;
    float2 v;
    v.x = __uint_as_float(f2tf32(w_dcn[((size_t)n * CIN + g * 8 + c) * 9 + k]));
    v.y = __uint_as_float(f2tf32(w_dcn[((size_t)n * CIN + g * 8 + c + 4) * 9 + k]));
    g_bfrag2[e] = v;
}

// ---------------------------------------------------------------------------
// Kernel A: implicit-GEMM 3x3 conv via mma.sync tf32 (R3 layout)
// ---------------------------------------------------------------------------
__device__ __forceinline__ void emit_off(int co, float v, int b, int p,
                                         const float* __restrict__ b_off) {
    v += __ldg(b_off + co);
    if (co < 144) {
        int g = co / 18, r = co % 18, k = r >> 1;
        float* dst = (r & 1) ? (g_scr + SCR_N) : g_scr;   // dx : dy
        dst[(b * GRP * KK9 + g * KK9 + k) * HW + p] = v;
    } else {
        int cm = co - 144, g = cm / 9, k = cm % 9;
        g_scr[2 * SCR_N + (b * GRP * KK9 + g * KK9 + k) * HW + p] =
            1.f / (1.f + expf(-v));
    }
}

__global__ __launch_bounds__(256)
void offset_conv_mma(const float* __restrict__ feat,
                     const float* __restrict__ b_off)
{
    const int tid  = threadIdx.x;
    const int warp = tid >> 5, lane = tid & 31;
    const int b  = blockIdx.y;
    const int p0 = blockIdx.x * 128;

    const int m0 = warp * 16 + (lane >> 2);
    const int pA = p0 + m0, pB = pA + 8;
    const int yA = pA / WW, xA = pA % WW;
    const int yB = pB / WW, xB = pB % WW;
    const float* fb = feat + (size_t)b * CIN * HW;

    float acc[27][4];
#pragma unroll
    for (int i = 0; i < 27; i++)
#pragma unroll
        for (int j = 0; j < 4; j++) acc[i][j] = 0.f;

    const int c = lane & 3;
    int ci0 = 0, kk0 = c;
    int ci1 = 0, kk1 = c + 4;

    auto samp2 = [&](int ci, int kk, float& vA, float& vB) {
        int dy = (kk > 5) ? 2 : ((kk > 2) ? 1 : 0);
        int dx = kk - dy * 3;
        int base = ci * HW;
        int gyA = yA + dy - 1, gxA = xA + dx - 1;
        int gyB = yB + dy - 1, gxB = xB + dx - 1;
        vA = ((unsigned)gyA < HH && (unsigned)gxA < WW)
               ? __ldg(fb + base + gyA * WW + gxA) : 0.f;
        vB = ((unsigned)gyB < HH && (unsigned)gxB < WW)
               ? __ldg(fb + base + gyB * WW + gxB) : 0.f;
    };

    uint32_t a[4];
    {
        float v0, v1, v2, v3;
        samp2(ci0, kk0, v0, v1);
        samp2(ci1, kk1, v2, v3);
        a[0] = f2tf32(v0); a[1] = f2tf32(v1);
        a[2] = f2tf32(v2); a[3] = f2tf32(v3);
    }

    const float2* bp = g_bfrag + lane;

#pragma unroll 1
    for (int t = 0; t < 72; t++) {
        uint32_t an[4] = {0u, 0u, 0u, 0u};
        if (t < 71) {
            if (kk0 == 0) kk0 = 8; else { kk0--; ci0++; }
            if (kk1 == 0) kk1 = 8; else { kk1--; ci1++; }
            float v0, v1, v2, v3;
            samp2(ci0, kk0, v0, v1);
            samp2(ci1, kk1, v2, v3);
            an[0] = f2tf32(v0); an[1] = f2tf32(v1);
            an[2] = f2tf32(v2); an[3] = f2tf32(v3);
        }

        const float2* bt = bp + (size_t)t * 27 * 32;
#pragma unroll
        for (int nt = 0; nt < 27; nt++) {
            float2 bb = __ldg(bt + nt * 32);
            MMA_TF32(acc[nt], a, __float_as_uint(bb.x), __float_as_uint(bb.y));
        }

        a[0] = an[0]; a[1] = an[1]; a[2] = an[2]; a[3] = an[3];
    }

#pragma unroll
    for (int nt = 0; nt < 27; nt++) {
#pragma unroll
        for (int i = 0; i < 4; i++) {
            int p  = (i >= 2) ? pB : pA;
            int co = nt * 8 + (lane & 3) * 2 + (i & 1);
            emit_off(co, acc[nt][i], b, p, b_off);
        }
    }
}

// ---------------------------------------------------------------------------
// Kernel B: modulated deformable conv via mma.sync tf32, NHWC gathers
// ---------------------------------------------------------------------------
__global__ __launch_bounds__(256)
void dcn_mma(const float* __restrict__ b_dcn,
             float* __restrict__ out)
{
    const int tid  = threadIdx.x;
    const int warp = tid >> 5, lane = tid & 31;
    const int b  = blockIdx.y;
    const int p0 = blockIdx.x * 128;

    const int m0 = warp * 16 + (lane >> 2);
    const int pA = p0 + m0, pB = pA + 8;
    const int yA = pA / WW, xA = pA % WW;
    const int yB = pB / WW, xB = pB % WW;

    const float* dyp = g_scr;
    const float* dxp = g_scr + SCR_N;
    const float* mp  = g_scr + 2*SCR_N;
    const float* xtb = g_xt + (size_t)b * HW * CIN;

    float acc[8][4];
#pragma unroll
    for (int i = 0; i < 8; i++)
#pragma unroll
        for (int j = 0; j < 4; j++) acc[i][j] = 0.f;

    const int c = lane & 3;

    // build A fragment for ktile t = g*9+k (NHWC gathers; quad-coalesced)
    auto build_a = [&](int t, uint32_t* a) {
        int g = t / 9, k = t - g * 9;
        int kdy = (k > 5) ? 2 : ((k > 2) ? 1 : 0);
        int kdx = k - kdy * 3;
        const int sb = (b * 72 + t) * HW;
        const float* xc = xtb + g * 8 + c;       // lane's channel base

        float vA0, vA4, vB0, vB4;
        {   // row pA
            float dy = __ldg(dyp + sb + pA), dx = __ldg(dxp + sb + pA);
            float mv = __ldg(mp + sb + pA);
            float py = (float)(yA + kdy - 1) + dy;
            float px = (float)(xA + kdx - 1) + dx;
            float fy = floorf(py), fx = floorf(px);
            int y0 = (int)fy, x0 = (int)fx;
            float ly = py - fy, lx = px - fx;
            bool vy0 = ((unsigned)y0 < HH), vy1 = ((unsigned)(y0+1) < HH);
            bool vx0 = ((unsigned)x0 < WW), vx1 = ((unsigned)(x0+1) < WW);
            int y0c = min(max(y0,0),HH-1), y1c = min(max(y0+1,0),HH-1);
            int x0c = min(max(x0,0),WW-1), x1c = min(max(x0+1,0),WW-1);
            float w00 = (1.f-ly)*(1.f-lx)*mv*((vy0&&vx0)?1.f:0.f);
            float w01 = (1.f-ly)*lx      *mv*((vy0&&vx1)?1.f:0.f);
            float w10 = ly      *(1.f-lx)*mv*((vy1&&vx0)?1.f:0.f);
            float w11 = ly      *lx      *mv*((vy1&&vx1)?1.f:0.f);
            int i00 = (y0c*WW+x0c)*CIN, i01 = (y0c*WW+x1c)*CIN;
            int i10 = (y1c*WW+x0c)*CIN, i11 = (y1c*WW+x1c)*CIN;
            vA0 = w00*__ldg(xc+i00)+w01*__ldg(xc+i01)+w10*__ldg(xc+i10)+w11*__ldg(xc+i11);
            vA4 = w00*__ldg(xc+i00+4)+w01*__ldg(xc+i01+4)+w10*__ldg(xc+i10+4)+w11*__ldg(xc+i11+4);
        }
        {   // row pB
            float dy = __ldg(dyp + sb + pB), dx = __ldg(dxp + sb + pB);
            float mv = __ldg(mp + sb + pB);
            float py = (float)(yB + kdy - 1) + dy;
            float px = (float)(xB + kdx - 1) + dx;
            float fy = floorf(py), fx = floorf(px);
            int y0 = (int)fy, x0 = (int)fx;
            float ly = py - fy, lx = px - fx;
            bool vy0 = ((unsigned)y0 < HH), vy1 = ((unsigned)(y0+1) < HH);
            bool vx0 = ((unsigned)x0 < WW), vx1 = ((unsigned)(x0+1) < WW);
            int y0c = min(max(y0,0),HH-1), y1c = min(max(y0+1,0),HH-1);
            int x0c = min(max(x0,0),WW-1), x1c = min(max(x0+1,0),WW-1);
            float w00 = (1.f-ly)*(1.f-lx)*mv*((vy0&&vx0)?1.f:0.f);
            float w01 = (1.f-ly)*lx      *mv*((vy0&&vx1)?1.f:0.f);
            float w10 = ly      *(1.f-lx)*mv*((vy1&&vx0)?1.f:0.f);
            float w11 = ly      *lx      *mv*((vy1&&vx1)?1.f:0.f);
            int i00 = (y0c*WW+x0c)*CIN, i01 = (y0c*WW+x1c)*CIN;
            int i10 = (y1c*WW+x0c)*CIN, i11 = (y1c*WW+x1c)*CIN;
            vB0 = w00*__ldg(xc+i00)+w01*__ldg(xc+i01)+w10*__ldg(xc+i10)+w11*__ldg(xc+i11);
            vB4 = w00*__ldg(xc+i00+4)+w01*__ldg(xc+i01+4)+w10*__ldg(xc+i10+4)+w11*__ldg(xc+i11+4);
        }
        a[0] = f2tf32(vA0); a[1] = f2tf32(vB0);
        a[2] = f2tf32(vA4); a[3] = f2tf32(vB4);
    };

    uint32_t a[4];
    build_a(0, a);

    const float2* bp = g_bfrag2 + lane;

#pragma unroll 1
    for (int t = 0; t < 72; t++) {
        uint32_t an[4] = {0u, 0u, 0u, 0u};
        if (t < 71) build_a(t + 1, an);

        const float2* bt = bp + (size_t)t * 8 * 32;
#pragma unroll
        for (int nt = 0; nt < 8; nt++) {
            float2 bb = __ldg(bt + nt * 32);
            MMA_TF32(acc[nt], a, __float_as_uint(bb.x), __float_as_uint(bb.y));
        }

        a[0] = an[0]; a[1] = an[1]; a[2] = an[2]; a[3] = an[3];
    }

#pragma unroll
    for (int nt = 0; nt < 8; nt++) {
#pragma unroll
        for (int e = 0; e < 4; e++) {
            int o = nt * 8 + c * 2 + (e & 1);
            int p = (e >= 2) ? pB : pA;
            out[((size_t)b * 64 + o) * HW + p] = acc[nt][e] + __ldg(b_dcn + o);
        }
    }
}

// ---------------------------------------------------------------------------
extern "C" void kernel_launch(void* const* d_in, const int* in_sizes, int n_in,
                              void* d_out, int out_size)
{
    const float* x     = (const float*)d_in[0];
    const float* feat  = (const float*)d_in[1];
    const float* w_off = (const float*)d_in[2];
    const float* b_off = (const float*)d_in[3];
    const float* w_dcn = (const float*)d_in[4];
    const float* b_dcn = (const float*)d_in[5];
    float* out = (float*)d_out;

    pack_w_kernel<<<(NBT + 255) / 256, 256>>>(w_off);
    pack_wd_kernel<<<(NBT2 + 255) / 256, 256>>>(w_dcn);

    dim3 gT(HW / 32, CIN / 32, BATCH);  // 800 x 2 x 4
    transpose_x_kernel<<<gT, 256>>>(x);

    dim3 gA(HW / 128, BATCH);           // 200 x 4
    offset_conv_mma<<<gA, 256>>>(feat, b_off);

    dim3 gB(HW / 128, BATCH);           // 200 x 4
    dcn_mma<<<gB, 256>>>(b_dcn, out);
}